// round 9
// baseline (speedup 1.0000x reference)
#include <cuda_runtime.h>
#include <cuda_bf16.h>
#include <cstdint>

// Problem constants: B=16, N=2048 -> NT=32768 nodes, C=H=256, E=262144, 3 layers.
#define NT   32768
#define HD   256
#define EDG  262144
#define NEG_SLOPE 0.2f
#define INV254 (1.0f / 254.0f)

// ---------------- device scratch ----------------
__device__ float g_h[NT * HD];                 // h = x @ W^T (fp32)
__device__ int8_t g_qa1[NT * HD];              // activation int8 hi digit
__device__ int8_t g_qa2[NT * HD];              // activation int8 lo digit (x254)
__device__ float  g_sa[NT];                    // activation row scales
__device__ int8_t g_qw1[3][HD * HD];           // weight int8 hi digits
__device__ int8_t g_qw2[3][HD * HD];           // weight int8 lo digits
__device__ float  g_sw[3][HD];                 // weight row scales
__device__ float g_sp[8][NT];                  // score partials
__device__ float g_si[NT];
__device__ float g_sj[NT];
__device__ float g_ex[EDG];
__device__ float g_scale[NT];
__device__ int   g_deg[NT];
__device__ int   g_off[NT + 1];
__device__ int   g_cur[NT];
__device__ int   g_srcs[EDG];
__device__ int   g_bsum[32];
__device__ int   g_bbase[32];
__device__ int   g_is64;

// ---------------- small helpers ----------------
__device__ __forceinline__ uint32_t smem_u32(const void* p) {
    uint32_t a;
    asm("{ .reg .u64 t; cvta.to.shared.u64 t, %1; cvt.u32.u64 %0, t; }" : "=r"(a) : "l"(p));
    return a;
}
__device__ __forceinline__ void ldsm4(uint32_t* r, uint32_t addr) {
    asm volatile("ldmatrix.sync.aligned.m8n8.x4.shared.b16 {%0,%1,%2,%3}, [%4];"
        : "=r"(r[0]), "=r"(r[1]), "=r"(r[2]), "=r"(r[3]) : "r"(addr));
}
__device__ __forceinline__ void mma_s8(int* c, const uint32_t* a, const uint32_t* b) {
    asm volatile(
        "mma.sync.aligned.m16n8k32.row.col.s32.s8.s8.s32 "
        "{%0,%1,%2,%3}, {%4,%5,%6,%7}, {%8,%9}, {%0,%1,%2,%3};"
        : "+r"(c[0]), "+r"(c[1]), "+r"(c[2]), "+r"(c[3])
        : "r"(a[0]), "r"(a[1]), "r"(a[2]), "r"(a[3]), "r"(b[0]), "r"(b[1]));
}
__device__ __forceinline__ void cpa16(uint32_t dst, const void* src) {
    asm volatile("cp.async.cg.shared.global [%0], [%1], 16;" :: "r"(dst), "l"(src));
}
// block-wide abs-max over 256 threads (8 warps)
__device__ __forceinline__ float block_absmax(float v, float* red) {
    int lane = threadIdx.x & 31, wid = threadIdx.x >> 5;
    #pragma unroll
    for (int o = 16; o > 0; o >>= 1) v = fmaxf(v, __shfl_xor_sync(~0u, v, o));
    if (lane == 0) red[wid] = v;
    __syncthreads();
    if (wid == 0) {
        float t = (lane < 8) ? red[lane] : 0.f;
        #pragma unroll
        for (int o = 4; o > 0; o >>= 1) t = fmaxf(t, __shfl_xor_sync(~0u, t, o));
        if (lane == 0) red[0] = t;
    }
    __syncthreads();
    return red[0];
}
// quantize one value given row absmax: q = v*127/max; d1 = rn(q); d2 = rn((q-d1)*254)
__device__ __forceinline__ void quant2(float v, float mx, int8_t& d1, int8_t& d2) {
    float inv = (mx > 0.f) ? 127.f / mx : 0.f;
    float q = v * inv;
    int a1 = __float2int_rn(q);
    int a2 = __float2int_rn((q - (float)a1) * 254.f);
    d1 = (int8_t)a1; d2 = (int8_t)a2;
}

// ---------------- edge index width detection ----------------
__global__ void k_detect(const int* ei32) {
    __shared__ int any;
    if (threadIdx.x == 0) any = 0;
    __syncthreads();
    int local = 0;
    for (int i = threadIdx.x; i < 4096; i += blockDim.x) local |= ei32[2 * i + 1];
    if (local) atomicOr(&any, 1);
    __syncthreads();
    if (threadIdx.x == 0) g_is64 = (any == 0) ? 1 : 0;
}
__device__ __forceinline__ int load_idx(const void* ei, int pos) {
    if (g_is64) return (int)((const long long*)ei)[pos];
    return ((const int*)ei)[pos];
}

// ---------------- CSR build ----------------
__global__ void k_zero_deg() { g_deg[blockIdx.x * 256 + threadIdx.x] = 0; }

__global__ void k_hist(const void* ei) {
    int e = blockIdx.x * 256 + threadIdx.x;
    atomicAdd(&g_deg[load_idx(ei, EDG + e)], 1);
}

__global__ void k_scan1() {
    __shared__ int wsum[32];
    int tid = threadIdx.x, lane = tid & 31, w = tid >> 5;
    int i = blockIdx.x * 1024 + tid;
    int v = g_deg[i];
    int inc = v;
    #pragma unroll
    for (int o = 1; o < 32; o <<= 1) { int t = __shfl_up_sync(~0u, inc, o); if (lane >= o) inc += t; }
    if (lane == 31) wsum[w] = inc;
    __syncthreads();
    if (w == 0) {
        int s = wsum[lane], iv = s;
        #pragma unroll
        for (int o = 1; o < 32; o <<= 1) { int t = __shfl_up_sync(~0u, iv, o); if (lane >= o) iv += t; }
        wsum[lane] = iv - s;
    }
    __syncthreads();
    int val = wsum[w] + inc;
    g_off[i + 1] = val;
    if (tid == 1023) g_bsum[blockIdx.x] = val;
}

__global__ void k_scan2() {
    int lane = threadIdx.x;
    int s = g_bsum[lane], iv = s;
    #pragma unroll
    for (int o = 1; o < 32; o <<= 1) { int t = __shfl_up_sync(~0u, iv, o); if (lane >= o) iv += t; }
    g_bbase[lane] = iv - s;
    if (lane == 0) g_off[0] = 0;
}

__global__ void k_scan3() {
    int i = blockIdx.x * 1024 + threadIdx.x;
    int off = g_off[i + 1] + g_bbase[blockIdx.x];
    g_off[i + 1] = off;
    g_cur[i] = off - g_deg[i];
}

__global__ void k_scatter(const void* ei) {
    int e = blockIdx.x * 256 + threadIdx.x;
    int src = load_idx(ei, e);
    int dst = load_idx(ei, EDG + e);
    g_srcs[atomicAdd(&g_cur[dst], 1)] = src;
}

// ---------------- quantization kernels ----------------
// weights: one block per W row (output channel), all 3 layers
__global__ void k_wquant(const float* __restrict__ W1,
                         const float* __restrict__ W2,
                         const float* __restrict__ W3) {
    __shared__ float red[8];
    int l = blockIdx.y, n = blockIdx.x, tid = threadIdx.x;
    const float* W = (l == 0) ? W1 : (l == 1) ? W2 : W3;
    float v = W[n * 256 + tid];
    float mx = block_absmax(fabsf(v), red);
    int8_t d1, d2;
    quant2(v, mx, d1, d2);
    g_qw1[l][n * 256 + tid] = d1;
    g_qw2[l][n * 256 + tid] = d2;
    if (tid == 0) g_sw[l][n] = mx / 127.f;
}

// initial activations: one block per node row
__global__ void k_aquant0(const float* __restrict__ x) {
    __shared__ float red[8];
    int row = blockIdx.x, tid = threadIdx.x;
    float v = x[(size_t)row * 256 + tid];
    float mx = block_absmax(fabsf(v), red);
    int8_t d1, d2;
    quant2(v, mx, d1, d2);
    g_qa1[(size_t)row * 256 + tid] = d1;
    g_qa2[(size_t)row * 256 + tid] = d2;
    if (tid == 0) g_sa[row] = mx / 127.f;
}

// ========== int8 dual-digit mma.sync GEMM, cp.async double-buffered ==========
// C[m,n] = sA_m*sB_n*(HI + MID/254), HI = sum A1B1, MID = sum (A1B2 + A2B1).
// CTA 128(M) x 128(N); K=256 int8 in 4 chunks of 64B; 8 warps 4M x 2N (32x64).
#define SROW   80
#define STILE  (128 * SROW)
#define OF_A1  0
#define OF_A2  STILE
#define OF_B1  (2 * STILE)
#define OF_B2  (3 * STILE)
#define BUFSZ  (4 * STILE)
#define SM_TOTAL (2 * BUFSZ)    // 81920 B dynamic

__global__ void __launch_bounds__(256) k_gemm_mma(const float* __restrict__ av, int layer) {
    extern __shared__ char sm[];
    uint32_t smb = smem_u32(sm);
    int tid = threadIdx.x, lane = tid & 31, wid = tid >> 5;
    int wm = wid & 3, wn = wid >> 2;
    int m0 = blockIdx.x * 128, n0 = blockIdx.y * 128;

    const int8_t* A1 = g_qa1 + (size_t)m0 * 256;
    const int8_t* A2 = g_qa2 + (size_t)m0 * 256;
    const int8_t* B1 = g_qw1[layer] + (size_t)n0 * 256;
    const int8_t* B2 = g_qw2[layer] + (size_t)n0 * 256;

    int lrow = tid >> 2, lc4 = tid & 3;   // 64 rows x 4 x 16B per tile; 2 row-halves

    // one K-chunk = 64 bytes per row of all 4 tiles
    #define CPA_CHUNK(bb, k0)                                                 \
        { _Pragma("unroll")                                                   \
          for (int i = 0; i < 2; i++) {                                       \
              int row = lrow + i * 64;                                        \
              uint32_t so = (bb) + (uint32_t)row * SROW + lc4 * 16;           \
              size_t go = (size_t)row * 256 + (k0) + lc4 * 16;                \
              cpa16(so + OF_A1, A1 + go);                                     \
              cpa16(so + OF_A2, A2 + go);                                     \
              cpa16(so + OF_B1, B1 + go);                                     \
              cpa16(so + OF_B2, B2 + go);                                     \
          }                                                                   \
          asm volatile("cp.async.commit_group;"); }

    // ldmatrix per-lane addresses (byte layout identical to bf16 k16 case)
    int quad = lane >> 3, qr = lane & 7;
    uint32_t aRel = (uint32_t)(wm * 32 + (quad & 1) * 8 + qr) * SROW + (uint32_t)((quad >> 1) * 16);
    uint32_t bRel = (uint32_t)(wn * 64 + (quad >> 1) * 8 + qr) * SROW + (uint32_t)((quad & 1) * 16);

    int hi[2][8][4], md[2][8][4];
    #pragma unroll
    for (int mi = 0; mi < 2; mi++)
        #pragma unroll
        for (int n8 = 0; n8 < 8; n8++)
            #pragma unroll
            for (int r = 0; r < 4; r++) { hi[mi][n8][r] = 0; md[mi][n8][r] = 0; }

    CPA_CHUNK(smb, 0);

    for (int c = 0; c < 4; c++) {
        uint32_t cur = smb + (uint32_t)(c & 1) * BUFSZ;
        if (c < 3) {
            CPA_CHUNK(smb + (uint32_t)((c + 1) & 1) * BUFSZ, (c + 1) * 64);
            asm volatile("cp.async.wait_group 1;" ::: "memory");
        } else {
            asm volatile("cp.async.wait_group 0;" ::: "memory");
        }
        __syncthreads();

        #pragma unroll
        for (int ks = 0; ks < 2; ks++) {     // k32 per step, 32B offset
            uint32_t a1f[2][4], a2f[2][4], b1f[4][4], b2f[4][4];
            #pragma unroll
            for (int mi = 0; mi < 2; mi++) {
                uint32_t ao = cur + aRel + (uint32_t)(mi * 16 * SROW + ks * 32);
                ldsm4(a1f[mi], ao + OF_A1);
                ldsm4(a2f[mi], ao + OF_A2);
            }
            #pragma unroll
            for (int nj = 0; nj < 4; nj++) {
                uint32_t bo = cur + bRel + (uint32_t)(nj * 16 * SROW + ks * 32);
                ldsm4(b1f[nj], bo + OF_B1);
                ldsm4(b2f[nj], bo + OF_B2);
            }
            #pragma unroll
            for (int mi = 0; mi < 2; mi++)
                #pragma unroll
                for (int nj = 0; nj < 4; nj++)
                    #pragma unroll
                    for (int h = 0; h < 2; h++) {
                        mma_s8(hi[mi][nj * 2 + h], a1f[mi], &b1f[nj][h * 2]);
                        mma_s8(md[mi][nj * 2 + h], a1f[mi], &b2f[nj][h * 2]);
                        mma_s8(md[mi][nj * 2 + h], a2f[mi], &b1f[nj][h * 2]);
                    }
        }
        __syncthreads();
    }

    // epilogue: dequantize, write fp32 h, fused score partials (race-free slots)
    int gid = lane >> 2, tig = lane & 3;
    int slot = blockIdx.y * 2 + wn;
    #pragma unroll
    for (int mi = 0; mi < 2; mi++) {
        int rbase = m0 + wm * 32 + mi * 16 + gid;
        float saA = g_sa[rbase], saB = g_sa[rbase + 8];
        float siA = 0.f, sjA = 0.f, siB = 0.f, sjB = 0.f;
        #pragma unroll
        for (int n8 = 0; n8 < 8; n8++) {
            int col = n0 + wn * 64 + n8 * 8 + tig * 2;
            float sb0 = g_sw[layer][col], sb1 = g_sw[layer][col + 1];
            float c0 = saA * sb0 * ((float)hi[mi][n8][0] + (float)md[mi][n8][0] * INV254);
            float c1 = saA * sb1 * ((float)hi[mi][n8][1] + (float)md[mi][n8][1] * INV254);
            float c2 = saB * sb0 * ((float)hi[mi][n8][2] + (float)md[mi][n8][2] * INV254);
            float c3 = saB * sb1 * ((float)hi[mi][n8][3] + (float)md[mi][n8][3] * INV254);
            float a0 = __ldg(av + col),       a1v = __ldg(av + col + 1);
            float b0 = __ldg(av + 256 + col), b1v = __ldg(av + 257 + col);
            siA = fmaf(c0, a0, fmaf(c1, a1v, siA));
            sjA = fmaf(c0, b0, fmaf(c1, b1v, sjA));
            siB = fmaf(c2, a0, fmaf(c3, a1v, siB));
            sjB = fmaf(c2, b0, fmaf(c3, b1v, sjB));
            float2 v0 = {c0, c1};
            float2 v1 = {c2, c3};
            *(float2*)(g_h + (size_t)rbase * 256 + col)       = v0;
            *(float2*)(g_h + (size_t)(rbase + 8) * 256 + col) = v1;
        }
        #pragma unroll
        for (int o = 1; o <= 2; o <<= 1) {
            siA += __shfl_xor_sync(~0u, siA, o);
            sjA += __shfl_xor_sync(~0u, sjA, o);
            siB += __shfl_xor_sync(~0u, siB, o);
            sjB += __shfl_xor_sync(~0u, sjB, o);
        }
        if (tig == 0) {
            g_sp[slot][rbase]         = siA;
            g_sp[4 + slot][rbase]     = sjA;
            g_sp[slot][rbase + 8]     = siB;
            g_sp[4 + slot][rbase + 8] = sjB;
        }
    }
}

// ---------------- combine score partials ----------------
__global__ void k_comb() {
    int i = blockIdx.x * 256 + threadIdx.x;
    g_si[i] = (g_sp[0][i] + g_sp[1][i]) + (g_sp[2][i] + g_sp[3][i]);
    g_sj[i] = (g_sp[4][i] + g_sp[5][i]) + (g_sp[6][i] + g_sp[7][i]);
}

// ---------------- segment softmax (8 lanes per dst node; deg ~ 8) ----------
__global__ void k_softmax() {
    int idx  = blockIdx.x * blockDim.x + threadIdx.x;
    int v    = idx >> 3;
    int l8   = idx & 7;
    if (v >= NT) return;
    unsigned gmask = 0xFFu << ((threadIdx.x & 31) & ~7);
    int s0 = g_off[v], s1 = g_off[v + 1];
    if (s0 == s1) { if (l8 == 0) g_scale[v] = 0.f; return; }
    float siv = g_si[v];
    float m = -1e30f;
    for (int e = s0 + l8; e < s1; e += 8) {
        float sc = siv + g_sj[g_srcs[e]];
        sc = (sc >= 0.f) ? sc : sc * NEG_SLOPE;
        g_ex[e] = sc;
        m = fmaxf(m, sc);
    }
    #pragma unroll
    for (int o = 4; o > 0; o >>= 1) m = fmaxf(m, __shfl_xor_sync(gmask, m, o));
    float sum = 0.f;
    for (int e = s0 + l8; e < s1; e += 8) {
        float ex = expf(g_ex[e] - m);
        g_ex[e] = ex;
        sum += ex;
    }
    #pragma unroll
    for (int o = 4; o > 0; o >>= 1) sum += __shfl_xor_sync(gmask, sum, o);
    if (l8 == 0) g_scale[v] = 1.f / (sum * (float)(s1 - s0));
}

// ------- aggregation + ELU; quantizes the row for the next layer ----------
__global__ void __launch_bounds__(256) k_agg(float* __restrict__ outExt, int last) {
    __shared__ float red[8];
    int v = blockIdx.x, tid = threadIdx.x;
    int s0 = g_off[v], s1 = g_off[v + 1];
    float acc = 0.f;
    int e = s0;
    for (; e + 4 <= s1; e += 4) {
        int i0 = g_srcs[e], i1 = g_srcs[e + 1], i2 = g_srcs[e + 2], i3 = g_srcs[e + 3];
        float w0 = g_ex[e], w1 = g_ex[e + 1], w2 = g_ex[e + 2], w3 = g_ex[e + 3];
        float v0 = g_h[(size_t)i0 * 256 + tid];
        float v1 = g_h[(size_t)i1 * 256 + tid];
        float v2 = g_h[(size_t)i2 * 256 + tid];
        float v3 = g_h[(size_t)i3 * 256 + tid];
        acc = fmaf(w0, v0, acc); acc = fmaf(w1, v1, acc);
        acc = fmaf(w2, v2, acc); acc = fmaf(w3, v3, acc);
    }
    for (; e < s1; e++)
        acc = fmaf(g_ex[e], g_h[(size_t)g_srcs[e] * 256 + tid], acc);
    float val = (s1 > s0) ? acc * g_scale[v] : 0.f;
    val = (val > 0.f) ? val : expm1f(val);
    if (last) {
        outExt[(size_t)v * 256 + tid] = val;
    } else {
        float mx = block_absmax(fabsf(val), red);
        int8_t d1, d2;
        quant2(val, mx, d1, d2);
        g_qa1[(size_t)v * 256 + tid] = d1;
        g_qa2[(size_t)v * 256 + tid] = d2;
        if (tid == 0) g_sa[v] = mx / 127.f;
    }
}

// ---------------- launch ----------------
extern "C" void kernel_launch(void* const* d_in, const int* in_sizes, int n_in,
                              void* d_out, int out_size) {
    const float* tf = (const float*)d_in[0];
    const void*  ei = d_in[1];
    const float* a[3] = {(const float*)d_in[3], (const float*)d_in[5], (const float*)d_in[7]};
    float* out = (float*)d_out;

    cudaFuncSetAttribute(k_gemm_mma, cudaFuncAttributeMaxDynamicSharedMemorySize, SM_TOTAL);

    // quantize weights + initial activations first (GEMM L0 depends only on these;
    // placing GEMM 6th lets ncu -s 5 -c 1 capture it)
    k_wquant<<<dim3(HD, 3), 256>>>((const float*)d_in[2],
                                   (const float*)d_in[4],
                                   (const float*)d_in[6]);
    k_aquant0<<<NT, 256>>>(tf);
    k_detect<<<1, 256>>>((const int*)ei);
    k_zero_deg<<<NT / 256, 256>>>();
    k_hist<<<EDG / 256, 256>>>(ei);

    k_gemm_mma<<<dim3(NT / 128, 2), 256, SM_TOTAL>>>(a[0], 0);   // 6th launch

    // CSR build completes before softmax needs it
    k_scan1<<<NT / 1024, 1024>>>();
    k_scan2<<<1, 32>>>();
    k_scan3<<<NT / 1024, 1024>>>();
    k_scatter<<<EDG / 256, 256>>>(ei);

    for (int l = 0; l < 3; l++) {
        if (l > 0) k_gemm_mma<<<dim3(NT / 128, 2), 256, SM_TOTAL>>>(a[l], l);
        k_comb<<<NT / 256, 256>>>();
        k_softmax<<<NT * 8 / 256, 256>>>();
        k_agg<<<NT, 256>>>(out, (l == 2) ? 1 : 0);
    }
}

// round 10
// speedup vs baseline: 1.5661x; 1.5661x over previous
#include <cuda_runtime.h>
#include <cuda_bf16.h>
#include <cstdint>

// Problem constants: B=16, N=2048 -> NT=32768 nodes, C=H=256, E=262144, 3 layers.
#define NT   32768
#define HD   256
#define EDG  262144
#define NEG_SLOPE 0.2f

// ---------------- device scratch ----------------
__device__ float g_h[NT * HD];                 // h = x @ W^T (fp32)
__device__ __nv_bfloat16 g_a1[NT * HD];        // activation hi split
__device__ __nv_bfloat16 g_a2[NT * HD];        // activation lo split
__device__ __nv_bfloat16 g_w1[3][HD * HD];     // weight hi splits (all layers)
__device__ __nv_bfloat16 g_w2[3][HD * HD];     // weight lo splits
__device__ float g_sp[8][NT];                  // score partials: si[y*2+wn], sj[4+y*2+wn]
__device__ float g_si[NT];
__device__ float g_sj[NT];
__device__ float g_ex[EDG];
__device__ float g_scale[NT];
__device__ int   g_deg[NT];
__device__ int   g_off[NT + 1];
__device__ int   g_cur[NT];
__device__ int   g_srcs[EDG];
__device__ int   g_bsum[32];
__device__ int   g_bbase[32];
__device__ int   g_is64;

// ---------------- small helpers ----------------
__device__ __forceinline__ uint32_t smem_u32(const void* p) {
    uint32_t a;
    asm("{ .reg .u64 t; cvta.to.shared.u64 t, %1; cvt.u32.u64 %0, t; }" : "=r"(a) : "l"(p));
    return a;
}
__device__ __forceinline__ void ldsm4(uint32_t* r, uint32_t addr) {
    asm volatile("ldmatrix.sync.aligned.m8n8.x4.shared.b16 {%0,%1,%2,%3}, [%4];"
        : "=r"(r[0]), "=r"(r[1]), "=r"(r[2]), "=r"(r[3]) : "r"(addr));
}
__device__ __forceinline__ void mma16816(float* c, const uint32_t* a, const uint32_t* b) {
    asm volatile(
        "mma.sync.aligned.m16n8k16.row.col.f32.bf16.bf16.f32 "
        "{%0,%1,%2,%3}, {%4,%5,%6,%7}, {%8,%9}, {%0,%1,%2,%3};"
        : "+f"(c[0]), "+f"(c[1]), "+f"(c[2]), "+f"(c[3])
        : "r"(a[0]), "r"(a[1]), "r"(a[2]), "r"(a[3]), "r"(b[0]), "r"(b[1]));
}
__device__ __forceinline__ void cpa16(uint32_t dst, const void* src) {
    asm volatile("cp.async.cg.shared.global [%0], [%1], 16;" :: "r"(dst), "l"(src));
}

// ---------------- edge index width detection ----------------
__global__ void k_detect(const int* ei32) {
    __shared__ int any;
    if (threadIdx.x == 0) any = 0;
    __syncthreads();
    int local = 0;
    for (int i = threadIdx.x; i < 4096; i += blockDim.x) local |= ei32[2 * i + 1];
    if (local) atomicOr(&any, 1);
    __syncthreads();
    if (threadIdx.x == 0) g_is64 = (any == 0) ? 1 : 0;
}
__device__ __forceinline__ int load_idx(const void* ei, int pos) {
    if (g_is64) return (int)((const long long*)ei)[pos];
    return ((const int*)ei)[pos];
}

// ---------------- CSR build ----------------
__global__ void k_zero_deg() { g_deg[blockIdx.x * 256 + threadIdx.x] = 0; }

__global__ void k_hist(const void* ei) {
    int e = blockIdx.x * 256 + threadIdx.x;
    atomicAdd(&g_deg[load_idx(ei, EDG + e)], 1);
}

__global__ void k_scan1() {
    __shared__ int wsum[32];
    int tid = threadIdx.x, lane = tid & 31, w = tid >> 5;
    int i = blockIdx.x * 1024 + tid;
    int v = g_deg[i];
    int inc = v;
    #pragma unroll
    for (int o = 1; o < 32; o <<= 1) { int t = __shfl_up_sync(~0u, inc, o); if (lane >= o) inc += t; }
    if (lane == 31) wsum[w] = inc;
    __syncthreads();
    if (w == 0) {
        int s = wsum[lane], iv = s;
        #pragma unroll
        for (int o = 1; o < 32; o <<= 1) { int t = __shfl_up_sync(~0u, iv, o); if (lane >= o) iv += t; }
        wsum[lane] = iv - s;
    }
    __syncthreads();
    int val = wsum[w] + inc;
    g_off[i + 1] = val;
    if (tid == 1023) g_bsum[blockIdx.x] = val;
}

__global__ void k_scan2() {
    int lane = threadIdx.x;
    int s = g_bsum[lane], iv = s;
    #pragma unroll
    for (int o = 1; o < 32; o <<= 1) { int t = __shfl_up_sync(~0u, iv, o); if (lane >= o) iv += t; }
    g_bbase[lane] = iv - s;
    if (lane == 0) g_off[0] = 0;
}

__global__ void k_scan3() {
    int i = blockIdx.x * 1024 + threadIdx.x;
    int off = g_off[i + 1] + g_bbase[blockIdx.x];
    g_off[i + 1] = off;
    g_cur[i] = off - g_deg[i];
}

__global__ void k_scatter(const void* ei) {
    int e = blockIdx.x * 256 + threadIdx.x;
    int src = load_idx(ei, e);
    int dst = load_idx(ei, EDG + e);
    g_srcs[atomicAdd(&g_cur[dst], 1)] = src;
}

// ---------------- weight splits for ALL layers in one launch ----------------
__global__ void k_wsplit_all(const float* __restrict__ W1,
                             const float* __restrict__ W2,
                             const float* __restrict__ W3) {
    int l = blockIdx.y;
    const float* W = (l == 0) ? W1 : (l == 1) ? W2 : W3;
    int i = blockIdx.x * 256 + threadIdx.x;
    float w = W[i];
    __nv_bfloat16 hi = __float2bfloat16_rn(w);
    g_w1[l][i] = hi;
    g_w2[l][i] = __float2bfloat16_rn(w - __bfloat162float(hi));
}

__global__ void k_asplit0(const float* __restrict__ x) {
    int i = blockIdx.x * 256 + threadIdx.x;
    float4 v = ((const float4*)x)[i];
    __nv_bfloat16 hx = __float2bfloat16_rn(v.x), hy = __float2bfloat16_rn(v.y);
    __nv_bfloat16 hz = __float2bfloat16_rn(v.z), hw = __float2bfloat16_rn(v.w);
    __nv_bfloat162 h01 = {hx, hy}, h23 = {hz, hw};
    __nv_bfloat162 l01 = {__float2bfloat16_rn(v.x - __bfloat162float(hx)),
                          __float2bfloat16_rn(v.y - __bfloat162float(hy))};
    __nv_bfloat162 l23 = {__float2bfloat16_rn(v.z - __bfloat162float(hz)),
                          __float2bfloat16_rn(v.w - __bfloat162float(hw))};
    uint2 p1 = {*(uint32_t*)&h01, *(uint32_t*)&h23};
    uint2 p2 = {*(uint32_t*)&l01, *(uint32_t*)&l23};
    *(uint2*)((char*)g_a1 + (size_t)i * 8) = p1;
    *(uint2*)((char*)g_a2 + (size_t)i * 8) = p2;
}

// ====== bf16 mma.sync GEMM, 3-stage cp.async pipeline (1 sync/chunk) ======
// C[NT,256] = A @ W^T via 3-term split (a1*b1 + a1*b2 + a2*b1), fp32 accum.
// CTA: 128(M) x 128(N), K=256 in 8 chunks of 32. 8 warps: 4M x 2N, warp 32x64.
#define SROW   80
#define STILE  (128 * SROW)
#define OF_A1  0
#define OF_A2  STILE
#define OF_B1  (2 * STILE)
#define OF_B2  (3 * STILE)
#define BUFSZ  (4 * STILE)      // 40960 B per stage
#define SM_TOTAL (3 * BUFSZ)    // 122880 B dynamic, 3 stages

__global__ void __launch_bounds__(256) k_gemm_mma(const float* __restrict__ av, int layer) {
    extern __shared__ char sm[];
    uint32_t smb = smem_u32(sm);
    int tid = threadIdx.x, lane = tid & 31, wid = tid >> 5;
    int wm = wid & 3, wn = wid >> 2;
    int m0 = blockIdx.x * 128, n0 = blockIdx.y * 128;

    const __nv_bfloat16* A1 = g_a1 + (size_t)m0 * 256;
    const __nv_bfloat16* A2 = g_a2 + (size_t)m0 * 256;
    const __nv_bfloat16* B1 = g_w1[layer] + (size_t)n0 * 256;
    const __nv_bfloat16* B2 = g_w2[layer] + (size_t)n0 * 256;

    int lrow = tid >> 2, lc4 = tid & 3;

    #define CPA_CHUNK(bb, k0)                                                 \
        { _Pragma("unroll")                                                   \
          for (int i = 0; i < 2; i++) {                                       \
              int row = lrow + i * 64;                                        \
              uint32_t so = (bb) + (uint32_t)row * SROW + lc4 * 16;           \
              size_t go = (size_t)row * 256 + (k0) + lc4 * 8;                 \
              cpa16(so + OF_A1, A1 + go);                                     \
              cpa16(so + OF_A2, A2 + go);                                     \
              cpa16(so + OF_B1, B1 + go);                                     \
              cpa16(so + OF_B2, B2 + go);                                     \
          }                                                                   \
          asm volatile("cp.async.commit_group;"); }

    int quad = lane >> 3, qr = lane & 7;
    uint32_t aRel = (uint32_t)(wm * 32 + (quad & 1) * 8 + qr) * SROW
                  + (uint32_t)((quad >> 1) * 16);
    uint32_t bRel = (uint32_t)(wn * 64 + (quad >> 1) * 8 + qr) * SROW
                  + (uint32_t)((quad & 1) * 16);

    float acc[2][8][4];
    #pragma unroll
    for (int mi = 0; mi < 2; mi++)
        #pragma unroll
        for (int n8 = 0; n8 < 8; n8++)
            #pragma unroll
            for (int r = 0; r < 4; r++) acc[mi][n8][r] = 0.f;

    // 3-stage prologue: chunks 0 and 1 in flight
    CPA_CHUNK(smb, 0);
    CPA_CHUNK(smb + BUFSZ, 32);

    int cb = 0, tb = 2;   // compute-buffer index, prefetch-target index
    for (int c = 0; c < 8; c++) {
        uint32_t cur = smb + (uint32_t)cb * BUFSZ;
        if (c < 7) { asm volatile("cp.async.wait_group 1;" ::: "memory"); }
        else       { asm volatile("cp.async.wait_group 0;" ::: "memory"); }
        __syncthreads();   // chunk c visible to all; all threads done with buffer tb
        if (c < 6) CPA_CHUNK(smb + (uint32_t)tb * BUFSZ, (c + 2) * 32);

        #pragma unroll
        for (int ks = 0; ks < 2; ks++) {
            uint32_t a1f[2][4], a2f[2][4], b1f[4][4], b2f[4][4];
            #pragma unroll
            for (int mi = 0; mi < 2; mi++) {
                uint32_t ao = cur + aRel + (uint32_t)(mi * 16 * SROW + ks * 32);
                ldsm4(a1f[mi], ao + OF_A1);
                ldsm4(a2f[mi], ao + OF_A2);
            }
            #pragma unroll
            for (int nj = 0; nj < 4; nj++) {
                uint32_t bo = cur + bRel + (uint32_t)(nj * 16 * SROW + ks * 32);
                ldsm4(b1f[nj], bo + OF_B1);
                ldsm4(b2f[nj], bo + OF_B2);
            }
            #pragma unroll
            for (int mi = 0; mi < 2; mi++)
                #pragma unroll
                for (int nj = 0; nj < 4; nj++)
                    #pragma unroll
                    for (int h = 0; h < 2; h++) {
                        float* C = acc[mi][nj * 2 + h];
                        mma16816(C, a1f[mi], &b1f[nj][h * 2]);
                        mma16816(C, a1f[mi], &b2f[nj][h * 2]);
                        mma16816(C, a2f[mi], &b1f[nj][h * 2]);
                    }
        }
        cb = (cb == 2) ? 0 : cb + 1;
        tb = (tb == 2) ? 0 : tb + 1;
    }

    // epilogue: write fp32 h + fused score partials (race-free slots)
    int gid = lane >> 2, tig = lane & 3;
    int slot = blockIdx.y * 2 + wn;
    #pragma unroll
    for (int mi = 0; mi < 2; mi++) {
        int rbase = m0 + wm * 32 + mi * 16 + gid;
        float siA = 0.f, sjA = 0.f, siB = 0.f, sjB = 0.f;
        #pragma unroll
        for (int n8 = 0; n8 < 8; n8++) {
            int col = n0 + wn * 64 + n8 * 8 + tig * 2;
            float a0 = __ldg(av + col),       a1v = __ldg(av + col + 1);
            float b0 = __ldg(av + 256 + col), b1v = __ldg(av + 257 + col);
            float c0 = acc[mi][n8][0], c1 = acc[mi][n8][1];
            float c2 = acc[mi][n8][2], c3 = acc[mi][n8][3];
            siA = fmaf(c0, a0, fmaf(c1, a1v, siA));
            sjA = fmaf(c0, b0, fmaf(c1, b1v, sjA));
            siB = fmaf(c2, a0, fmaf(c3, a1v, siB));
            sjB = fmaf(c2, b0, fmaf(c3, b1v, sjB));
            float2 v0 = {c0, c1};
            float2 v1 = {c2, c3};
            *(float2*)(g_h + (size_t)rbase * 256 + col)       = v0;
            *(float2*)(g_h + (size_t)(rbase + 8) * 256 + col) = v1;
        }
        #pragma unroll
        for (int o = 1; o <= 2; o <<= 1) {
            siA += __shfl_xor_sync(~0u, siA, o);
            sjA += __shfl_xor_sync(~0u, sjA, o);
            siB += __shfl_xor_sync(~0u, siB, o);
            sjB += __shfl_xor_sync(~0u, sjB, o);
        }
        if (tig == 0) {
            g_sp[slot][rbase]         = siA;
            g_sp[4 + slot][rbase]     = sjA;
            g_sp[slot][rbase + 8]     = siB;
            g_sp[4 + slot][rbase + 8] = sjB;
        }
    }
}

// ---------------- combine score partials ----------------
__global__ void k_comb() {
    int i = blockIdx.x * 256 + threadIdx.x;
    g_si[i] = (g_sp[0][i] + g_sp[1][i]) + (g_sp[2][i] + g_sp[3][i]);
    g_sj[i] = (g_sp[4][i] + g_sp[5][i]) + (g_sp[6][i] + g_sp[7][i]);
}

// ---------------- segment softmax (8 lanes per dst node; deg ~ 8) ----------
__global__ void k_softmax() {
    int idx  = blockIdx.x * blockDim.x + threadIdx.x;
    int v    = idx >> 3;
    int l8   = idx & 7;
    if (v >= NT) return;
    unsigned gmask = 0xFFu << ((threadIdx.x & 31) & ~7);
    int s0 = g_off[v], s1 = g_off[v + 1];
    if (s0 == s1) { if (l8 == 0) g_scale[v] = 0.f; return; }
    float siv = g_si[v];
    float m = -1e30f;
    for (int e = s0 + l8; e < s1; e += 8) {
        float sc = siv + g_sj[g_srcs[e]];
        sc = (sc >= 0.f) ? sc : sc * NEG_SLOPE;
        g_ex[e] = sc;
        m = fmaxf(m, sc);
    }
    #pragma unroll
    for (int o = 4; o > 0; o >>= 1) m = fmaxf(m, __shfl_xor_sync(gmask, m, o));
    float sum = 0.f;
    for (int e = s0 + l8; e < s1; e += 8) {
        float ex = expf(g_ex[e] - m);
        g_ex[e] = ex;
        sum += ex;
    }
    #pragma unroll
    for (int o = 4; o > 0; o >>= 1) sum += __shfl_xor_sync(gmask, sum, o);
    if (l8 == 0) g_scale[v] = 1.f / (sum * (float)(s1 - s0));
}

// ---------------- aggregation + ELU; writes bf16 splits for next layer ------
__global__ void __launch_bounds__(256) k_agg(float* __restrict__ outExt, int last) {
    int v = blockIdx.x, tid = threadIdx.x;
    int s0 = g_off[v], s1 = g_off[v + 1];
    float acc = 0.f;
    int e = s0;
    for (; e + 4 <= s1; e += 4) {
        int i0 = g_srcs[e], i1 = g_srcs[e + 1], i2 = g_srcs[e + 2], i3 = g_srcs[e + 3];
        float w0 = g_ex[e], w1 = g_ex[e + 1], w2 = g_ex[e + 2], w3 = g_ex[e + 3];
        float v0 = g_h[(size_t)i0 * 256 + tid];
        float v1 = g_h[(size_t)i1 * 256 + tid];
        float v2 = g_h[(size_t)i2 * 256 + tid];
        float v3 = g_h[(size_t)i3 * 256 + tid];
        acc = fmaf(w0, v0, acc); acc = fmaf(w1, v1, acc);
        acc = fmaf(w2, v2, acc); acc = fmaf(w3, v3, acc);
    }
    for (; e < s1; e++)
        acc = fmaf(g_ex[e], g_h[(size_t)g_srcs[e] * 256 + tid], acc);
    float val = (s1 > s0) ? acc * g_scale[v] : 0.f;
    val = (val > 0.f) ? val : expm1f(val);
    if (last) {
        outExt[(size_t)v * 256 + tid] = val;
    } else {
        __nv_bfloat16 hi = __float2bfloat16_rn(val);
        g_a1[(size_t)v * 256 + tid] = hi;
        g_a2[(size_t)v * 256 + tid] = __float2bfloat16_rn(val - __bfloat162float(hi));
    }
}

// ---------------- launch ----------------
extern "C" void kernel_launch(void* const* d_in, const int* in_sizes, int n_in,
                              void* d_out, int out_size) {
    const float* tf = (const float*)d_in[0];
    const void*  ei = d_in[1];
    const float* a[3] = {(const float*)d_in[3], (const float*)d_in[5], (const float*)d_in[7]};
    float* out = (float*)d_out;

    cudaFuncSetAttribute(k_gemm_mma, cudaFuncAttributeMaxDynamicSharedMemorySize, SM_TOTAL);

    // splits first; GEMM L0 is the 4th launch (ncu captures launch #4)
    k_wsplit_all<<<dim3(HD * HD / 256, 3), 256>>>((const float*)d_in[2],
                                                  (const float*)d_in[4],
                                                  (const float*)d_in[6]);
    k_asplit0<<<NT * HD / 4 / 256, 256>>>(tf);
    k_detect<<<1, 256>>>((const int*)ei);

    k_gemm_mma<<<dim3(NT / 128, 2), 256, SM_TOTAL>>>(a[0], 0);   // 4th launch

    // CSR build (finishes before softmax needs it)
    k_zero_deg<<<NT / 256, 256>>>();
    k_hist<<<EDG / 256, 256>>>(ei);
    k_scan1<<<NT / 1024, 1024>>>();
    k_scan2<<<1, 32>>>();
    k_scan3<<<NT / 1024, 1024>>>();
    k_scatter<<<EDG / 256, 256>>>(ei);

    for (int l = 0; l < 3; l++) {
        if (l > 0) k_gemm_mma<<<dim3(NT / 128, 2), 256, SM_TOTAL>>>(a[l], l);
        k_comb<<<NT / 256, 256>>>();
        k_softmax<<<NT * 8 / 256, 256>>>();
        k_agg<<<NT, 256>>>(out, (l == 2) ? 1 : 0);
    }
}

// round 11
// speedup vs baseline: 1.6571x; 1.0581x over previous
#include <cuda_runtime.h>
#include <cuda_bf16.h>
#include <cstdint>

// Problem constants: B=16, N=2048 -> NT=32768 nodes, C=H=256, E=262144, 3 layers.
#define NT   32768
#define HD   256
#define EDG  262144
#define NEG_SLOPE 0.2f

// ---------------- device scratch ----------------
__device__ float g_h[NT * HD];                 // h = x @ W^T (fp32)
__device__ __nv_bfloat16 g_a1[NT * HD];        // activation hi split
__device__ __nv_bfloat16 g_a2[NT * HD];        // activation lo split
__device__ __nv_bfloat16 g_w1[3][HD * HD];     // weight hi splits (all layers)
__device__ __nv_bfloat16 g_w2[3][HD * HD];     // weight lo splits
__device__ float g_sp[8][NT];                  // score partials: si[y*2+wn], sj[4+y*2+wn]
__device__ float g_si[NT];
__device__ float g_sj[NT];
__device__ float g_ex[EDG];
__device__ float g_scale[NT];
__device__ int   g_deg[NT];
__device__ int   g_off[NT + 1];
__device__ int   g_cur[NT];
__device__ int   g_srcs[EDG];
__device__ int   g_bsum[32];
__device__ int   g_bbase[32];
__device__ int   g_is64;

// ---------------- small helpers ----------------
__device__ __forceinline__ uint32_t smem_u32(const void* p) {
    uint32_t a;
    asm("{ .reg .u64 t; cvta.to.shared.u64 t, %1; cvt.u32.u64 %0, t; }" : "=r"(a) : "l"(p));
    return a;
}
__device__ __forceinline__ void ldsm4(uint32_t* r, uint32_t addr) {
    asm volatile("ldmatrix.sync.aligned.m8n8.x4.shared.b16 {%0,%1,%2,%3}, [%4];"
        : "=r"(r[0]), "=r"(r[1]), "=r"(r[2]), "=r"(r[3]) : "r"(addr));
}
__device__ __forceinline__ void mma16816(float* c, const uint32_t* a, const uint32_t* b) {
    asm volatile(
        "mma.sync.aligned.m16n8k16.row.col.f32.bf16.bf16.f32 "
        "{%0,%1,%2,%3}, {%4,%5,%6,%7}, {%8,%9}, {%0,%1,%2,%3};"
        : "+f"(c[0]), "+f"(c[1]), "+f"(c[2]), "+f"(c[3])
        : "r"(a[0]), "r"(a[1]), "r"(a[2]), "r"(a[3]), "r"(b[0]), "r"(b[1]));
}
__device__ __forceinline__ void cpa16(uint32_t dst, const void* src) {
    asm volatile("cp.async.cg.shared.global [%0], [%1], 16;" :: "r"(dst), "l"(src));
}

// ---------------- edge index width detection ----------------
__global__ void k_detect(const int* ei32) {
    __shared__ int any;
    if (threadIdx.x == 0) any = 0;
    __syncthreads();
    int local = 0;
    for (int i = threadIdx.x; i < 4096; i += blockDim.x) local |= ei32[2 * i + 1];
    if (local) atomicOr(&any, 1);
    __syncthreads();
    if (threadIdx.x == 0) g_is64 = (any == 0) ? 1 : 0;
}
__device__ __forceinline__ int load_idx(const void* ei, int pos) {
    if (g_is64) return (int)((const long long*)ei)[pos];
    return ((const int*)ei)[pos];
}

// ---------------- CSR build ----------------
__global__ void k_zero_deg() { g_deg[blockIdx.x * 256 + threadIdx.x] = 0; }

__global__ void k_hist(const void* ei) {
    int e = blockIdx.x * 256 + threadIdx.x;
    atomicAdd(&g_deg[load_idx(ei, EDG + e)], 1);
}

__global__ void k_scan1() {
    __shared__ int wsum[32];
    int tid = threadIdx.x, lane = tid & 31, w = tid >> 5;
    int i = blockIdx.x * 1024 + tid;
    int v = g_deg[i];
    int inc = v;
    #pragma unroll
    for (int o = 1; o < 32; o <<= 1) { int t = __shfl_up_sync(~0u, inc, o); if (lane >= o) inc += t; }
    if (lane == 31) wsum[w] = inc;
    __syncthreads();
    if (w == 0) {
        int s = wsum[lane], iv = s;
        #pragma unroll
        for (int o = 1; o < 32; o <<= 1) { int t = __shfl_up_sync(~0u, iv, o); if (lane >= o) iv += t; }
        wsum[lane] = iv - s;
    }
    __syncthreads();
    int val = wsum[w] + inc;
    g_off[i + 1] = val;
    if (tid == 1023) g_bsum[blockIdx.x] = val;
}

__global__ void k_scan2() {
    int lane = threadIdx.x;
    int s = g_bsum[lane], iv = s;
    #pragma unroll
    for (int o = 1; o < 32; o <<= 1) { int t = __shfl_up_sync(~0u, iv, o); if (lane >= o) iv += t; }
    g_bbase[lane] = iv - s;
    if (lane == 0) g_off[0] = 0;
}

__global__ void k_scan3() {
    int i = blockIdx.x * 1024 + threadIdx.x;
    int off = g_off[i + 1] + g_bbase[blockIdx.x];
    g_off[i + 1] = off;
    g_cur[i] = off - g_deg[i];
}

__global__ void k_scatter(const void* ei) {
    int e = blockIdx.x * 256 + threadIdx.x;
    int src = load_idx(ei, e);
    int dst = load_idx(ei, EDG + e);
    g_srcs[atomicAdd(&g_cur[dst], 1)] = src;
}

// ---------------- weight splits for ALL layers in one launch ----------------
__global__ void k_wsplit_all(const float* __restrict__ W1,
                             const float* __restrict__ W2,
                             const float* __restrict__ W3) {
    int l = blockIdx.y;
    const float* W = (l == 0) ? W1 : (l == 1) ? W2 : W3;
    int i = blockIdx.x * 256 + threadIdx.x;
    float w = W[i];
    __nv_bfloat16 hi = __float2bfloat16_rn(w);
    g_w1[l][i] = hi;
    g_w2[l][i] = __float2bfloat16_rn(w - __bfloat162float(hi));
}

__global__ void k_asplit0(const float* __restrict__ x) {
    int i = blockIdx.x * 256 + threadIdx.x;
    float4 v = ((const float4*)x)[i];
    __nv_bfloat16 hx = __float2bfloat16_rn(v.x), hy = __float2bfloat16_rn(v.y);
    __nv_bfloat16 hz = __float2bfloat16_rn(v.z), hw = __float2bfloat16_rn(v.w);
    __nv_bfloat162 h01 = {hx, hy}, h23 = {hz, hw};
    __nv_bfloat162 l01 = {__float2bfloat16_rn(v.x - __bfloat162float(hx)),
                          __float2bfloat16_rn(v.y - __bfloat162float(hy))};
    __nv_bfloat162 l23 = {__float2bfloat16_rn(v.z - __bfloat162float(hz)),
                          __float2bfloat16_rn(v.w - __bfloat162float(hw))};
    uint2 p1 = {*(uint32_t*)&h01, *(uint32_t*)&h23};
    uint2 p2 = {*(uint32_t*)&l01, *(uint32_t*)&l23};
    *(uint2*)((char*)g_a1 + (size_t)i * 8) = p1;
    *(uint2*)((char*)g_a2 + (size_t)i * 8) = p2;
}

// ====== bf16 mma.sync GEMM, 2-stage cp.async, 2 CTAs/SM ======
// C[NT,256] = A @ W^T via 3-term split (a1*b1 + a1*b2 + a2*b1), fp32 accum.
// CTA: 128(M) x 128(N), K=256 in 8 chunks of 32. 8 warps: 4M x 2N, warp 32x64.
// __launch_bounds__(256, 2) caps regs at 128 -> 2 CTAs/SM (16 warps) for
// latency hiding; smem 2 x 40960 = 81920 B/CTA (163840/SM fits 228KB).
#define SROW   80
#define STILE  (128 * SROW)
#define OF_A1  0
#define OF_A2  STILE
#define OF_B1  (2 * STILE)
#define OF_B2  (3 * STILE)
#define BUFSZ  (4 * STILE)      // 40960 B per stage
#define SM_TOTAL (2 * BUFSZ)    // 81920 B dynamic

__global__ void __launch_bounds__(256, 2) k_gemm_mma(const float* __restrict__ av, int layer) {
    extern __shared__ char sm[];
    uint32_t smb = smem_u32(sm);
    int tid = threadIdx.x, lane = tid & 31, wid = tid >> 5;
    int wm = wid & 3, wn = wid >> 2;
    int m0 = blockIdx.x * 128, n0 = blockIdx.y * 128;

    const __nv_bfloat16* A1 = g_a1 + (size_t)m0 * 256;
    const __nv_bfloat16* A2 = g_a2 + (size_t)m0 * 256;
    const __nv_bfloat16* B1 = g_w1[layer] + (size_t)n0 * 256;
    const __nv_bfloat16* B2 = g_w2[layer] + (size_t)n0 * 256;

    int lrow = tid >> 2, lc4 = tid & 3;

    #define CPA_CHUNK(bb, k0)                                                 \
        { _Pragma("unroll")                                                   \
          for (int i = 0; i < 2; i++) {                                       \
              int row = lrow + i * 64;                                        \
              uint32_t so = (bb) + (uint32_t)row * SROW + lc4 * 16;           \
              size_t go = (size_t)row * 256 + (k0) + lc4 * 8;                 \
              cpa16(so + OF_A1, A1 + go);                                     \
              cpa16(so + OF_A2, A2 + go);                                     \
              cpa16(so + OF_B1, B1 + go);                                     \
              cpa16(so + OF_B2, B2 + go);                                     \
          }                                                                   \
          asm volatile("cp.async.commit_group;"); }

    int quad = lane >> 3, qr = lane & 7;
    uint32_t aRel = (uint32_t)(wm * 32 + (quad & 1) * 8 + qr) * SROW
                  + (uint32_t)((quad >> 1) * 16);
    uint32_t bRel = (uint32_t)(wn * 64 + (quad >> 1) * 8 + qr) * SROW
                  + (uint32_t)((quad & 1) * 16);

    float acc[2][8][4];
    #pragma unroll
    for (int mi = 0; mi < 2; mi++)
        #pragma unroll
        for (int n8 = 0; n8 < 8; n8++)
            #pragma unroll
            for (int r = 0; r < 4; r++) acc[mi][n8][r] = 0.f;

    CPA_CHUNK(smb, 0);

    for (int c = 0; c < 8; c++) {
        uint32_t cur = smb + (uint32_t)(c & 1) * BUFSZ;
        if (c < 7) {
            CPA_CHUNK(smb + (uint32_t)((c + 1) & 1) * BUFSZ, (c + 1) * 32);
            asm volatile("cp.async.wait_group 1;" ::: "memory");
        } else {
            asm volatile("cp.async.wait_group 0;" ::: "memory");
        }
        __syncthreads();

        #pragma unroll
        for (int ks = 0; ks < 2; ks++) {
            uint32_t a1f[2][4], a2f[2][4], b1f[4][4], b2f[4][4];
            #pragma unroll
            for (int mi = 0; mi < 2; mi++) {
                uint32_t ao = cur + aRel + (uint32_t)(mi * 16 * SROW + ks * 32);
                ldsm4(a1f[mi], ao + OF_A1);
                ldsm4(a2f[mi], ao + OF_A2);
            }
            #pragma unroll
            for (int nj = 0; nj < 4; nj++) {
                uint32_t bo = cur + bRel + (uint32_t)(nj * 16 * SROW + ks * 32);
                ldsm4(b1f[nj], bo + OF_B1);
                ldsm4(b2f[nj], bo + OF_B2);
            }
            #pragma unroll
            for (int mi = 0; mi < 2; mi++)
                #pragma unroll
                for (int nj = 0; nj < 4; nj++)
                    #pragma unroll
                    for (int h = 0; h < 2; h++) {
                        float* C = acc[mi][nj * 2 + h];
                        mma16816(C, a1f[mi], &b1f[nj][h * 2]);
                        mma16816(C, a1f[mi], &b2f[nj][h * 2]);
                        mma16816(C, a2f[mi], &b1f[nj][h * 2]);
                    }
        }
        __syncthreads();   // protect cur buffer before refill at c+1
    }

    // epilogue: write fp32 h + fused score partials (race-free slots)
    int gid = lane >> 2, tig = lane & 3;
    int slot = blockIdx.y * 2 + wn;
    #pragma unroll
    for (int mi = 0; mi < 2; mi++) {
        int rbase = m0 + wm * 32 + mi * 16 + gid;
        float siA = 0.f, sjA = 0.f, siB = 0.f, sjB = 0.f;
        #pragma unroll
        for (int n8 = 0; n8 < 8; n8++) {
            int col = n0 + wn * 64 + n8 * 8 + tig * 2;
            float a0 = __ldg(av + col),       a1v = __ldg(av + col + 1);
            float b0 = __ldg(av + 256 + col), b1v = __ldg(av + 257 + col);
            float c0 = acc[mi][n8][0], c1 = acc[mi][n8][1];
            float c2 = acc[mi][n8][2], c3 = acc[mi][n8][3];
            siA = fmaf(c0, a0, fmaf(c1, a1v, siA));
            sjA = fmaf(c0, b0, fmaf(c1, b1v, sjA));
            siB = fmaf(c2, a0, fmaf(c3, a1v, siB));
            sjB = fmaf(c2, b0, fmaf(c3, b1v, sjB));
            float2 v0 = {c0, c1};
            float2 v1 = {c2, c3};
            *(float2*)(g_h + (size_t)rbase * 256 + col)       = v0;
            *(float2*)(g_h + (size_t)(rbase + 8) * 256 + col) = v1;
        }
        #pragma unroll
        for (int o = 1; o <= 2; o <<= 1) {
            siA += __shfl_xor_sync(~0u, siA, o);
            sjA += __shfl_xor_sync(~0u, sjA, o);
            siB += __shfl_xor_sync(~0u, siB, o);
            sjB += __shfl_xor_sync(~0u, sjB, o);
        }
        if (tig == 0) {
            g_sp[slot][rbase]         = siA;
            g_sp[4 + slot][rbase]     = sjA;
            g_sp[slot][rbase + 8]     = siB;
            g_sp[4 + slot][rbase + 8] = sjB;
        }
    }
}

// ---------------- combine score partials ----------------
__global__ void k_comb() {
    int i = blockIdx.x * 256 + threadIdx.x;
    g_si[i] = (g_sp[0][i] + g_sp[1][i]) + (g_sp[2][i] + g_sp[3][i]);
    g_sj[i] = (g_sp[4][i] + g_sp[5][i]) + (g_sp[6][i] + g_sp[7][i]);
}

// ---------------- segment softmax (8 lanes per dst node; deg ~ 8) ----------
__global__ void k_softmax() {
    int idx  = blockIdx.x * blockDim.x + threadIdx.x;
    int v    = idx >> 3;
    int l8   = idx & 7;
    if (v >= NT) return;
    unsigned gmask = 0xFFu << ((threadIdx.x & 31) & ~7);
    int s0 = g_off[v], s1 = g_off[v + 1];
    if (s0 == s1) { if (l8 == 0) g_scale[v] = 0.f; return; }
    float siv = g_si[v];
    float m = -1e30f;
    for (int e = s0 + l8; e < s1; e += 8) {
        float sc = siv + g_sj[g_srcs[e]];
        sc = (sc >= 0.f) ? sc : sc * NEG_SLOPE;
        g_ex[e] = sc;
        m = fmaxf(m, sc);
    }
    #pragma unroll
    for (int o = 4; o > 0; o >>= 1) m = fmaxf(m, __shfl_xor_sync(gmask, m, o));
    float sum = 0.f;
    for (int e = s0 + l8; e < s1; e += 8) {
        float ex = expf(g_ex[e] - m);
        g_ex[e] = ex;
        sum += ex;
    }
    #pragma unroll
    for (int o = 4; o > 0; o >>= 1) sum += __shfl_xor_sync(gmask, sum, o);
    if (l8 == 0) g_scale[v] = 1.f / (sum * (float)(s1 - s0));
}

// ---------------- aggregation + ELU; writes bf16 splits for next layer ------
__global__ void __launch_bounds__(256) k_agg(float* __restrict__ outExt, int last) {
    int v = blockIdx.x, tid = threadIdx.x;
    int s0 = g_off[v], s1 = g_off[v + 1];
    float acc = 0.f;
    int e = s0;
    for (; e + 4 <= s1; e += 4) {
        int i0 = g_srcs[e], i1 = g_srcs[e + 1], i2 = g_srcs[e + 2], i3 = g_srcs[e + 3];
        float w0 = g_ex[e], w1 = g_ex[e + 1], w2 = g_ex[e + 2], w3 = g_ex[e + 3];
        float v0 = g_h[(size_t)i0 * 256 + tid];
        float v1 = g_h[(size_t)i1 * 256 + tid];
        float v2 = g_h[(size_t)i2 * 256 + tid];
        float v3 = g_h[(size_t)i3 * 256 + tid];
        acc = fmaf(w0, v0, acc); acc = fmaf(w1, v1, acc);
        acc = fmaf(w2, v2, acc); acc = fmaf(w3, v3, acc);
    }
    for (; e < s1; e++)
        acc = fmaf(g_ex[e], g_h[(size_t)g_srcs[e] * 256 + tid], acc);
    float val = (s1 > s0) ? acc * g_scale[v] : 0.f;
    val = (val > 0.f) ? val : expm1f(val);
    if (last) {
        outExt[(size_t)v * 256 + tid] = val;
    } else {
        __nv_bfloat16 hi = __float2bfloat16_rn(val);
        g_a1[(size_t)v * 256 + tid] = hi;
        g_a2[(size_t)v * 256 + tid] = __float2bfloat16_rn(val - __bfloat162float(hi));
    }
}

// ---------------- launch ----------------
extern "C" void kernel_launch(void* const* d_in, const int* in_sizes, int n_in,
                              void* d_out, int out_size) {
    const float* tf = (const float*)d_in[0];
    const void*  ei = d_in[1];
    const float* a[3] = {(const float*)d_in[3], (const float*)d_in[5], (const float*)d_in[7]};
    float* out = (float*)d_out;

    cudaFuncSetAttribute(k_gemm_mma, cudaFuncAttributeMaxDynamicSharedMemorySize, SM_TOTAL);

    // splits first; GEMM L0 is the 4th launch (ncu captures launch #4)
    k_wsplit_all<<<dim3(HD * HD / 256, 3), 256>>>((const float*)d_in[2],
                                                  (const float*)d_in[4],
                                                  (const float*)d_in[6]);
    k_asplit0<<<NT * HD / 4 / 256, 256>>>(tf);
    k_detect<<<1, 256>>>((const int*)ei);

    k_gemm_mma<<<dim3(NT / 128, 2), 256, SM_TOTAL>>>(a[0], 0);   // 4th launch

    // CSR build (finishes before softmax needs it)
    k_zero_deg<<<NT / 256, 256>>>();
    k_hist<<<EDG / 256, 256>>>(ei);
    k_scan1<<<NT / 1024, 1024>>>();
    k_scan2<<<1, 32>>>();
    k_scan3<<<NT / 1024, 1024>>>();
    k_scatter<<<EDG / 256, 256>>>(ei);

    for (int l = 0; l < 3; l++) {
        if (l > 0) k_gemm_mma<<<dim3(NT / 128, 2), 256, SM_TOTAL>>>(a[l], l);
        k_comb<<<NT / 256, 256>>>();
        k_softmax<<<NT * 8 / 256, 256>>>();
        k_agg<<<NT, 256>>>(out, (l == 2) ? 1 : 0);
    }
}